// round 9
// baseline (speedup 1.0000x reference)
#include <cuda_runtime.h>
#include <cuda_fp16.h>
#include <math.h>
#include <stdint.h>

#define NTOK 65536
#define DIM 256
#define HID 1024
#define NE 8
#define MAXTILES 519

// ---------------- device scratch ----------------
__device__ float g_xavg[16 * 256];
__device__ float g_avglogit[16 * NE];
__device__ int   g_cnt[NE];
__device__ int   g_tileBase[NE + 1];
__device__ int   g_tok[NE * NTOK];
__device__ float g_gate[NTOK];
__device__ __half g_xh[(size_t)NTOK * DIM];               // fp16 cast of x (token-major)
__device__ __half g_W1h[(size_t)NE * HID * DIM];          // W1 transposed: [e][n(1024)][k(256)]
__device__ __half g_W2h[(size_t)NE * DIM * HID];          // W2 transposed: [e][n(256)][k(1024)]
__device__ __half g_hidden[(size_t)MAXTILES * 128 * HID]; // [tile][m(128)][HID]

// ---------------- helpers ----------------
__device__ __forceinline__ uint32_t pk2h(float a, float b) {
    __half2 h = __floats2half2_rn(a, b);
    return *(uint32_t*)&h;
}
__device__ __forceinline__ uint32_t smem_u32(const void* p) {
    uint32_t a;
    asm("{ .reg .u64 t; cvta.to.shared.u64 t, %1; cvt.u32.u64 %0, t; }" : "=r"(a) : "l"(p));
    return a;
}
__device__ __forceinline__ void mma_f16(float* d, const uint32_t* a, const uint32_t* b) {
    asm volatile(
        "mma.sync.aligned.m16n8k16.row.col.f32.f16.f16.f32 "
        "{%0,%1,%2,%3}, {%4,%5,%6,%7}, {%8,%9}, {%0,%1,%2,%3};"
        : "+f"(d[0]), "+f"(d[1]), "+f"(d[2]), "+f"(d[3])
        : "r"(a[0]), "r"(a[1]), "r"(a[2]), "r"(a[3]), "r"(b[0]), "r"(b[1]));
}
__device__ __forceinline__ void cpa16(uint32_t dst, const void* src) {
    asm volatile("cp.async.cg.shared.global [%0], [%1], 16;" :: "r"(dst), "l"(src));
}
#define CP_COMMIT() asm volatile("cp.async.commit_group;" ::: "memory")
#define CP_WAIT1()  asm volatile("cp.async.wait_group 1;" ::: "memory")
__device__ __forceinline__ void ldsm4(uint32_t* r, uint32_t addr) {
    asm volatile("ldmatrix.sync.aligned.m8n8.x4.shared.b16 {%0,%1,%2,%3}, [%4];"
                 : "=r"(r[0]), "=r"(r[1]), "=r"(r[2]), "=r"(r[3]) : "r"(addr));
}
__device__ __forceinline__ void ldsm2(uint32_t* r, uint32_t addr) {
    asm volatile("ldmatrix.sync.aligned.m8n8.x2.shared.b16 {%0,%1}, [%2];"
                 : "=r"(r[0]), "=r"(r[1]) : "r"(addr));
}

// ---------------- K0a: x -> fp16 cast + fused adaptive avg pool ----------------
// One block per (b,c) spatial plane: 4096 contiguous floats.
__global__ void convXpool_kernel(const float* __restrict__ x) {
    int c = blockIdx.x, b = blockIdx.y;
    size_t base4 = ((size_t)b * DIM + c) * 1024;  // in float4 units
    const float4* p = (const float4*)x + base4;
    uint2* o = (uint2*)g_xh + base4;
    int tid = threadIdx.x;
    float s = 0.f;
#pragma unroll
    for (int j = 0; j < 4; j++) {
        float4 v = p[tid + 256 * j];
        s += v.x + v.y + v.z + v.w;
        uint2 u;
        u.x = pk2h(v.x, v.y);
        u.y = pk2h(v.z, v.w);
        o[tid + 256 * j] = u;
    }
#pragma unroll
    for (int off = 16; off > 0; off >>= 1) s += __shfl_xor_sync(0xFFFFFFFFu, s, off);
    __shared__ float ws[8];
    if ((tid & 31) == 0) ws[tid >> 5] = s;
    __syncthreads();
    if (tid == 0) {
        float t = 0.f;
#pragma unroll
        for (int i = 0; i < 8; i++) t += ws[i];
        g_xavg[b * 256 + c] = t * (1.0f / 4096.0f);
    }
}

// ---------------- K0b: weight transpose + fp16: W[e][k][n] -> Wt[e][n][k] ----------------
__device__ __forceinline__ void convW_body(const float* __restrict__ W, __half* __restrict__ Wt,
                                           int K, int N) {
    __shared__ float sm[32][33];
    int e = blockIdx.z;
    int n0 = blockIdx.x * 32, k0 = blockIdx.y * 32;
    const float* Wp = W + (size_t)e * K * N;
    __half* Wtp = Wt + (size_t)e * K * N;
    int tx = threadIdx.x, ty = threadIdx.y;
#pragma unroll
    for (int j = 0; j < 4; j++)
        sm[ty + 8 * j][tx] = Wp[(size_t)(k0 + ty + 8 * j) * N + n0 + tx];
    __syncthreads();
#pragma unroll
    for (int j = 0; j < 4; j++)
        Wtp[(size_t)(n0 + ty + 8 * j) * K + k0 + tx] = __float2half(sm[tx][ty + 8 * j]);
}
__global__ void convW1_kernel(const float* __restrict__ W) { convW_body(W, g_W1h, DIM, HID); }
__global__ void convW2_kernel(const float* __restrict__ W) { convW_body(W, g_W2h, HID, DIM); }

// ---------------- K2: avg logits + zero counters ----------------
__global__ void prep_kernel(const float* __restrict__ Wa, const float* __restrict__ ba) {
    int t = threadIdx.x;
    if (t < NE) g_cnt[t] = 0;
    if (t < 128) {
        int b = t >> 3, e = t & 7;
        float acc = 0.f;
        for (int c = 0; c < 256; c++) acc += g_xavg[b * 256 + c] * Wa[c * 8 + e];
        g_avglogit[t] = acc + ba[e];
    }
}

// ---------------- K3: router ----------------
__global__ void router_kernel(const float* __restrict__ x, const float* __restrict__ noise,
                              const float* __restrict__ Wr, const float* __restrict__ br,
                              const float* __restrict__ Wn, const float* __restrict__ bn) {
    __shared__ float sWr[2048], sWn[2048];
    __shared__ float sbr[8], sbn[8], sAvg[8];
    __shared__ int scnt[8], sbase[8];
    int tid = threadIdx.x;
    int i = blockIdx.x * 256 + tid;
    int b = i >> 12;
    for (int j = tid; j < 2048; j += 256) { sWr[j] = Wr[j]; sWn[j] = Wn[j]; }
    if (tid < 8) {
        sbr[tid] = br[tid]; sbn[tid] = bn[tid];
        sAvg[tid] = g_avglogit[b * 8 + tid];
        scnt[tid] = 0;
    }
    __syncthreads();

    float ar[8] = {0, 0, 0, 0, 0, 0, 0, 0};
    float an[8] = {0, 0, 0, 0, 0, 0, 0, 0};
    const float4* xp = (const float4*)(x + (size_t)i * DIM);

#define ROUT_STEP(xc, kk)                                                            \
    {                                                                                \
        float4 w0 = *(const float4*)&sWr[(kk) * 8];                                  \
        float4 w1 = *(const float4*)&sWr[(kk) * 8 + 4];                              \
        float4 u0 = *(const float4*)&sWn[(kk) * 8];                                  \
        float4 u1 = *(const float4*)&sWn[(kk) * 8 + 4];                              \
        ar[0] += (xc) * w0.x; ar[1] += (xc) * w0.y; ar[2] += (xc) * w0.z;            \
        ar[3] += (xc) * w0.w; ar[4] += (xc) * w1.x; ar[5] += (xc) * w1.y;            \
        ar[6] += (xc) * w1.z; ar[7] += (xc) * w1.w;                                  \
        an[0] += (xc) * u0.x; an[1] += (xc) * u0.y; an[2] += (xc) * u0.z;            \
        an[3] += (xc) * u0.w; an[4] += (xc) * u1.x; an[5] += (xc) * u1.y;            \
        an[6] += (xc) * u1.z; an[7] += (xc) * u1.w;                                  \
    }

#pragma unroll 4
    for (int k4 = 0; k4 < 64; k4++) {
        float4 xv = xp[k4];
        int k = k4 * 4;
        ROUT_STEP(xv.x, k + 0);
        ROUT_STEP(xv.y, k + 1);
        ROUT_STEP(xv.z, k + 2);
        ROUT_STEP(xv.w, k + 3);
    }
#undef ROUT_STEP

    float noisy[8];
    const float* np = noise + (size_t)i * 8;
#pragma unroll
    for (int e = 0; e < 8; e++) {
        float lg = ar[e] + sbr[e] + sAvg[e];
        float z = an[e] + sbn[e];
        float sp = fmaxf(z, 0.f) + log1pf(expf(-fabsf(z)));
        noisy[e] = lg + np[e] * sp;
    }
    int i1 = 0; float v1 = noisy[0];
#pragma unroll
    for (int e = 1; e < 8; e++) if (noisy[e] > v1) { v1 = noisy[e]; i1 = e; }
    int i2 = -1; float v2 = -INFINITY;
#pragma unroll
    for (int e = 0; e < 8; e++) if (e != i1 && noisy[e] > v2) { v2 = noisy[e]; i2 = e; }

    float t = expf(v2 - v1);
    int es; float g;
    if (i1 > i2) { es = i1; g = 1.f / (1.f + t); }
    else         { es = i2; g = t / (1.f + t); }

    int pl = atomicAdd(&scnt[es], 1);
    __syncthreads();
    if (tid < 8) sbase[tid] = atomicAdd(&g_cnt[tid], scnt[tid]);
    __syncthreads();
    g_tok[es * NTOK + sbase[es] + pl] = i;
    g_gate[i] = g;
}

// ---------------- K4: per-expert tile offsets ----------------
__global__ void scan_kernel() {
    if (threadIdx.x == 0) {
        int tb = 0;
        for (int e = 0; e < NE; e++) {
            g_tileBase[e] = tb;
            tb += (g_cnt[e] + 127) >> 7;
        }
        g_tileBase[NE] = tb;
    }
}

// ---------------- tile metadata helper ----------------
__device__ __forceinline__ void tile_meta(int bx, int* sMeta) {
    int e = -1, rem = 0, tokbase = 0;
    if (bx < g_tileBase[NE]) {
        e = 0;
        while (bx >= g_tileBase[e + 1]) e++;
        int lt = bx - g_tileBase[e];
        tokbase = e * NTOK + lt * 128;
        rem = g_cnt[e] - lt * 128;
    }
    sMeta[0] = e; sMeta[1] = tokbase; sMeta[2] = rem;
}

// ==================== GEMM core: 512 threads, CTA tile 128x256, BK=64, 3 stages ====
// Stage: A [128 rows][128 B] swizzled at +0; B [256 rows][128 B] at +16384.
// Stage stride 49152 B (48 KB), 3 stages = 144 KB.
// Warp grid: wm = wid>>2 (4, M 32 each), wn = wid&3 (4, N 64 each).
#define STAGE_BYTES 49152
#define SMEM_GEMM (3 * STAGE_BYTES)

#define GEMM_LOAD(st, cc)                                                     \
    do {                                                                      \
        uint32_t _ab = smemBase + (st) * STAGE_BYTES;                         \
        int _kt = (cc) * 64;                                                  \
        _Pragma("unroll")                                                     \
        for (int i = 0; i < 2; i++) cpa16(_ab + aDst[i], aSrc[i] + _kt);      \
        _Pragma("unroll")                                                     \
        for (int i = 0; i < 4; i++) cpa16(_ab + bDst[i], bSrc[i] + _kt);      \
    } while (0)

#define GEMM_COMPUTE(st)                                                      \
    do {                                                                      \
        uint32_t _ab = smemBase + (st) * STAGE_BYTES;                         \
        _Pragma("unroll")                                                     \
        for (int ks = 0; ks < 4; ks++) {                                      \
            uint32_t af[2][4], bf[8][2];                                      \
            _Pragma("unroll")                                                 \
            for (int mt = 0; mt < 2; mt++)                                    \
                ldsm4(af[mt], _ab + aLdBase + mt * 2048 +                     \
                              ((uint32_t)((2 * ks + hiA) ^ r7A) << 4));       \
            _Pragma("unroll")                                                 \
            for (int nt = 0; nt < 8; nt++)                                    \
                ldsm2(bf[nt], _ab + 16384 + bLdBase + nt * 1024 +             \
                              ((uint32_t)((2 * ks + hiB) ^ r7B) << 4));       \
            _Pragma("unroll")                                                 \
            for (int mt = 0; mt < 2; mt++)                                    \
                _Pragma("unroll")                                             \
                for (int nt = 0; nt < 8; nt++)                                \
                    mma_f16(acc[mt][nt], af[mt], bf[nt]);                     \
        }                                                                     \
    } while (0)

// ================ gemmA: hidden = relu(X @ W1 + b1), CTA 128x256 ================
__global__ void __launch_bounds__(512, 1)
gemmA_kernel(const float* __restrict__ b1) {
    extern __shared__ __align__(16) char dsm[];
    __shared__ int rowTok[128];
    __shared__ int sMeta[3];

    const int tid = threadIdx.x;
    if (tid == 0) tile_meta(blockIdx.x, sMeta);
    __syncthreads();
    const int e = sMeta[0];
    if (e < 0) return;
    const int rem = sMeta[2];
    const int n0 = blockIdx.y * 256;
    if (tid < 128) rowTok[tid] = (tid < rem) ? g_tok[sMeta[1] + tid] : g_tok[sMeta[1]];
    __syncthreads();

    const int lane = tid & 31, wid = tid >> 5;
    const int wm = wid >> 2, wn = wid & 3;
    const int mbase = wm * 32, nbase = wn * 64;
    const int lr = lane >> 2, lc = lane & 3;

    const uint32_t smemBase = smem_u32(dsm);

    // cp.async offsets: A 2/thread (128x64 fp16), B 4/thread (256x64 fp16)
    const __half* aSrc[2];
    const __half* bSrc[4];
    uint32_t aDst[2], bDst[4];
#pragma unroll
    for (int i = 0; i < 2; i++) {
        int idx = tid + 512 * i;
        int m = idx >> 3, ch = idx & 7;
        aSrc[i] = g_xh + (size_t)rowTok[m] * DIM + ch * 8;
        aDst[i] = (uint32_t)(m * 128 + ((ch ^ (m & 7)) << 4));
    }
#pragma unroll
    for (int i = 0; i < 4; i++) {
        int idx = tid + 512 * i;
        int n = idx >> 3, ch = idx & 7;
        bSrc[i] = g_W1h + (size_t)e * HID * DIM + (size_t)(n0 + n) * DIM + ch * 8;
        bDst[i] = (uint32_t)(16384 + n * 128 + ((ch ^ (n & 7)) << 4));
    }
    const int r7A = lane & 7, hiA = lane >> 4;
    const uint32_t aLdBase = (uint32_t)((mbase + (lane & 15)) * 128);
    const int r7B = lane & 7, hiB = (lane >> 3) & 1;
    const uint32_t bLdBase = (uint32_t)((nbase + (lane & 7)) * 128);

    float acc[2][8][4];
#pragma unroll
    for (int a = 0; a < 2; a++)
#pragma unroll
        for (int b = 0; b < 8; b++)
#pragma unroll
            for (int c = 0; c < 4; c++) acc[a][b][c] = 0.f;

    // 3-stage pipeline, NC = 4 chunks of K=64
    GEMM_LOAD(0, 0); CP_COMMIT();
    GEMM_LOAD(1, 1); CP_COMMIT();
#pragma unroll
    for (int c = 0; c < 4; c++) {
        CP_WAIT1();
        __syncthreads();
        if (c + 2 < 4) GEMM_LOAD((c + 2) % 3, c + 2);
        CP_COMMIT();
        GEMM_COMPUTE(c % 3);
    }

    // epilogue: acc -> Hs (half2, row stride 132 u32) -> coalesced STG
    __syncthreads();
    uint32_t* Hs = (uint32_t*)dsm;
    const float* bg = b1 + (size_t)e * HID + n0;
#pragma unroll
    for (int nt = 0; nt < 8; nt++) {
        int col = nbase + nt * 8 + lc * 2;
        float bb0 = __ldg(bg + col), bb1 = __ldg(bg + col + 1);
        int chn = col >> 1;
#pragma unroll
        for (int mt = 0; mt < 2; mt++) {
            int r0 = mbase + mt * 16 + lr;
            Hs[r0 * 132 + chn] = pk2h(fmaxf(acc[mt][nt][0] + bb0, 0.f),
                                      fmaxf(acc[mt][nt][1] + bb1, 0.f));
            Hs[(r0 + 8) * 132 + chn] = pk2h(fmaxf(acc[mt][nt][2] + bb0, 0.f),
                                            fmaxf(acc[mt][nt][3] + bb1, 0.f));
        }
    }
    __syncthreads();
    __half* hp = g_hidden + ((size_t)blockIdx.x * 128) * HID + n0;
#pragma unroll
    for (int j = 0; j < 8; j++) {
        int U = tid + 512 * j;
        int row = U >> 5, c4 = U & 31;
        uint4 v = *(const uint4*)&Hs[row * 132 + c4 * 4];
        *(uint4*)(hp + (size_t)row * HID + c4 * 8) = v;
    }
}

// ================ gemmB: out = (hidden @ W2 + b2) * gate, CTA 128x256 (full DIM) ====
__global__ void __launch_bounds__(512, 1)
gemmB_kernel(const float* __restrict__ b2, float* __restrict__ out) {
    extern __shared__ __align__(16) char dsm[];
    __shared__ int rowTok[128];
    __shared__ float sGate[128];
    __shared__ int sMeta[3];

    const int tid = threadIdx.x;
    if (tid == 0) tile_meta(blockIdx.x, sMeta);
    __syncthreads();
    const int e = sMeta[0];
    if (e < 0) return;
    const int rem = sMeta[2];
    if (tid < 128) {
        int tr = (tid < rem) ? g_tok[sMeta[1] + tid] : -1;
        rowTok[tid] = tr;
        sGate[tid] = (tr >= 0) ? g_gate[tr] : 0.f;
    }
    __syncthreads();

    const int lane = tid & 31, wid = tid >> 5;
    const int wm = wid >> 2, wn = wid & 3;
    const int mbase = wm * 32, nbase = wn * 64;
    const int lr = lane >> 2, lc = lane & 3;

    const uint32_t smemBase = smem_u32(dsm);

    const __half* aSrc[2];
    const __half* bSrc[4];
    uint32_t aDst[2], bDst[4];
#pragma unroll
    for (int i = 0; i < 2; i++) {
        int idx = tid + 512 * i;
        int m = idx >> 3, ch = idx & 7;
        aSrc[i] = g_hidden + ((size_t)blockIdx.x * 128 + m) * HID + ch * 8;
        aDst[i] = (uint32_t)(m * 128 + ((ch ^ (m & 7)) << 4));
    }
#pragma unroll
    for (int i = 0; i < 4; i++) {
        int idx = tid + 512 * i;
        int n = idx >> 3, ch = idx & 7;
        bSrc[i] = g_W2h + (size_t)e * DIM * HID + (size_t)n * HID + ch * 8;
        bDst[i] = (uint32_t)(16384 + n * 128 + ((ch ^ (n & 7)) << 4));
    }
    const int r7A = lane & 7, hiA = lane >> 4;
    const uint32_t aLdBase = (uint32_t)((mbase + (lane & 15)) * 128);
    const int r7B = lane & 7, hiB = (lane >> 3) & 1;
    const uint32_t bLdBase = (uint32_t)((nbase + (lane & 7)) * 128);

    float acc[2][8][4];
#pragma unroll
    for (int a = 0; a < 2; a++)
#pragma unroll
        for (int b = 0; b < 8; b++)
#pragma unroll
            for (int c = 0; c < 4; c++) acc[a][b][c] = 0.f;

    // 3-stage pipeline, NC = 16 chunks of K=64
    GEMM_LOAD(0, 0); CP_COMMIT();
    GEMM_LOAD(1, 1); CP_COMMIT();
    for (int c = 0; c < 16; c++) {
        CP_WAIT1();
        __syncthreads();
        if (c + 2 < 16) GEMM_LOAD((c + 2) % 3, c + 2);
        CP_COMMIT();
        GEMM_COMPUTE(c % 3);
    }

    // epilogue: bias + gate -> scattered out rows (full DIM per tile)
    const float* bg = b2 + (size_t)e * DIM;
#pragma unroll
    for (int nt = 0; nt < 8; nt++) {
        int col = nbase + nt * 8 + lc * 2;
        float bb0 = __ldg(bg + col), bb1 = __ldg(bg + col + 1);
#pragma unroll
        for (int mt = 0; mt < 2; mt++) {
            int r0 = mbase + mt * 16 + lr;
            if (r0 < rem) {
                float g = sGate[r0];
                float2 o;
                o.x = (acc[mt][nt][0] + bb0) * g;
                o.y = (acc[mt][nt][1] + bb1) * g;
                *(float2*)&out[(size_t)rowTok[r0] * DIM + col] = o;
            }
            int r1 = r0 + 8;
            if (r1 < rem) {
                float g = sGate[r1];
                float2 o;
                o.x = (acc[mt][nt][2] + bb0) * g;
                o.y = (acc[mt][nt][3] + bb1) * g;
                *(float2*)&out[(size_t)rowTok[r1] * DIM + col] = o;
            }
        }
    }
}

// ---------------- launch ----------------
extern "C" void kernel_launch(void* const* d_in, const int* in_sizes, int n_in,
                              void* d_out, int out_size) {
    const float* x     = (const float*)d_in[0];
    const float* noise = (const float*)d_in[1];
    const float* Wr    = (const float*)d_in[2];
    const float* br    = (const float*)d_in[3];
    const float* Wa    = (const float*)d_in[4];
    const float* ba    = (const float*)d_in[5];
    const float* Wn    = (const float*)d_in[6];
    const float* bn    = (const float*)d_in[7];
    const float* W1    = (const float*)d_in[8];
    const float* b1    = (const float*)d_in[9];
    const float* W2    = (const float*)d_in[10];
    const float* b2    = (const float*)d_in[11];
    float* out = (float*)d_out;

    cudaFuncSetAttribute(gemmA_kernel, cudaFuncAttributeMaxDynamicSharedMemorySize, SMEM_GEMM);
    cudaFuncSetAttribute(gemmB_kernel, cudaFuncAttributeMaxDynamicSharedMemorySize, SMEM_GEMM);

    convXpool_kernel<<<dim3(256, 16), 256>>>(x);
    convW1_kernel<<<dim3(HID / 32, DIM / 32, NE), dim3(32, 8)>>>(W1);
    convW2_kernel<<<dim3(DIM / 32, HID / 32, NE), dim3(32, 8)>>>(W2);
    prep_kernel<<<1, 128>>>(Wa, ba);
    router_kernel<<<256, 256>>>(x, noise, Wr, br, Wn, bn);
    scan_kernel<<<1, 1>>>();
    gemmA_kernel<<<dim3(MAXTILES, 4), 512, SMEM_GEMM>>>(b1);
    gemmB_kernel<<<MAXTILES, 512, SMEM_GEMM>>>(b2, out);
}

// round 11
// speedup vs baseline: 1.1938x; 1.1938x over previous
#include <cuda_runtime.h>
#include <cuda_fp16.h>
#include <math.h>
#include <stdint.h>

#define NTOK 65536
#define DIM 256
#define HID 1024
#define NE 8
#define MAXTILES 519

// ---------------- device scratch ----------------
__device__ float g_xavg[16 * 256];
__device__ float g_avglogit[16 * NE];
__device__ int   g_cnt[NE];
__device__ int   g_tileBase[NE + 1];
__device__ int   g_tok[NE * NTOK];
__device__ float g_gate[NTOK];
__device__ __half g_xh[(size_t)NTOK * DIM];               // fp16 cast of x (token-major)
__device__ __half g_W1h[(size_t)NE * HID * DIM];          // W1 transposed: [e][n(1024)][k(256)]
__device__ __half g_W2h[(size_t)NE * DIM * HID];          // W2 transposed: [e][n(256)][k(1024)]
__device__ __half g_hidden[(size_t)MAXTILES * 128 * HID]; // [tile][m(128)][HID]

// ---------------- helpers ----------------
__device__ __forceinline__ uint32_t pk2h(float a, float b) {
    __half2 h = __floats2half2_rn(a, b);
    return *(uint32_t*)&h;
}
__device__ __forceinline__ uint32_t smem_u32(const void* p) {
    uint32_t a;
    asm("{ .reg .u64 t; cvta.to.shared.u64 t, %1; cvt.u32.u64 %0, t; }" : "=r"(a) : "l"(p));
    return a;
}
__device__ __forceinline__ void mma_f16(float* d, const uint32_t* a, const uint32_t* b) {
    asm volatile(
        "mma.sync.aligned.m16n8k16.row.col.f32.f16.f16.f32 "
        "{%0,%1,%2,%3}, {%4,%5,%6,%7}, {%8,%9}, {%0,%1,%2,%3};"
        : "+f"(d[0]), "+f"(d[1]), "+f"(d[2]), "+f"(d[3])
        : "r"(a[0]), "r"(a[1]), "r"(a[2]), "r"(a[3]), "r"(b[0]), "r"(b[1]));
}
__device__ __forceinline__ void cpa16(uint32_t dst, const void* src) {
    asm volatile("cp.async.cg.shared.global [%0], [%1], 16;" :: "r"(dst), "l"(src));
}
#define CP_COMMIT() asm volatile("cp.async.commit_group;" ::: "memory")
#define CP_WAIT1()  asm volatile("cp.async.wait_group 1;" ::: "memory")
__device__ __forceinline__ void ldsm4(uint32_t* r, uint32_t addr) {
    asm volatile("ldmatrix.sync.aligned.m8n8.x4.shared.b16 {%0,%1,%2,%3}, [%4];"
                 : "=r"(r[0]), "=r"(r[1]), "=r"(r[2]), "=r"(r[3]) : "r"(addr));
}
__device__ __forceinline__ void ldsm2(uint32_t* r, uint32_t addr) {
    asm volatile("ldmatrix.sync.aligned.m8n8.x2.shared.b16 {%0,%1}, [%2];"
                 : "=r"(r[0]), "=r"(r[1]) : "r"(addr));
}

// ---------------- K0a: x -> fp16 cast + fused adaptive avg pool ----------------
__global__ void convXpool_kernel(const float* __restrict__ x) {
    int c = blockIdx.x, b = blockIdx.y;
    size_t base4 = ((size_t)b * DIM + c) * 1024;  // float4 units
    const float4* p = (const float4*)x + base4;
    uint2* o = (uint2*)g_xh + base4;
    int tid = threadIdx.x;
    float s = 0.f;
#pragma unroll
    for (int j = 0; j < 4; j++) {
        float4 v = p[tid + 256 * j];
        s += v.x + v.y + v.z + v.w;
        uint2 u;
        u.x = pk2h(v.x, v.y);
        u.y = pk2h(v.z, v.w);
        o[tid + 256 * j] = u;
    }
#pragma unroll
    for (int off = 16; off > 0; off >>= 1) s += __shfl_xor_sync(0xFFFFFFFFu, s, off);
    __shared__ float ws[8];
    if ((tid & 31) == 0) ws[tid >> 5] = s;
    __syncthreads();
    if (tid == 0) {
        float t = 0.f;
#pragma unroll
        for (int i = 0; i < 8; i++) t += ws[i];
        g_xavg[b * 256 + c] = t * (1.0f / 4096.0f);
    }
}

// ---------------- K0b: weight transpose + fp16: W[e][k][n] -> Wt[e][n][k] ----------------
__device__ __forceinline__ void convW_body(const float* __restrict__ W, __half* __restrict__ Wt,
                                           int K, int N) {
    __shared__ float sm[32][33];
    int e = blockIdx.z;
    int n0 = blockIdx.x * 32, k0 = blockIdx.y * 32;
    const float* Wp = W + (size_t)e * K * N;
    __half* Wtp = Wt + (size_t)e * K * N;
    int tx = threadIdx.x, ty = threadIdx.y;
#pragma unroll
    for (int j = 0; j < 4; j++)
        sm[ty + 8 * j][tx] = Wp[(size_t)(k0 + ty + 8 * j) * N + n0 + tx];
    __syncthreads();
#pragma unroll
    for (int j = 0; j < 4; j++)
        Wtp[(size_t)(n0 + ty + 8 * j) * K + k0 + tx] = __float2half(sm[tx][ty + 8 * j]);
}
__global__ void convW1_kernel(const float* __restrict__ W) { convW_body(W, g_W1h, DIM, HID); }
__global__ void convW2_kernel(const float* __restrict__ W) { convW_body(W, g_W2h, HID, DIM); }

// ---------------- K2: avg logits (parallel) + zero counters ----------------
// one block per (b, e); 256 threads reduce over c
__global__ void prep_kernel(const float* __restrict__ Wa, const float* __restrict__ ba) {
    int be = blockIdx.x;            // 0..127
    int b = be >> 3, e = be & 7;
    int tid = threadIdx.x;
    float v = g_xavg[b * 256 + tid] * Wa[tid * 8 + e];
#pragma unroll
    for (int off = 16; off > 0; off >>= 1) v += __shfl_xor_sync(0xFFFFFFFFu, v, off);
    __shared__ float ws[8];
    if ((tid & 31) == 0) ws[tid >> 5] = v;
    __syncthreads();
    if (tid == 0) {
        float t = 0.f;
#pragma unroll
        for (int i = 0; i < 8; i++) t += ws[i];
        g_avglogit[be] = t + ba[e];
    }
    if (be == 0 && tid < NE) g_cnt[tid] = 0;
}

// ---------------- K3: router ----------------
__global__ void router_kernel(const float* __restrict__ x, const float* __restrict__ noise,
                              const float* __restrict__ Wr, const float* __restrict__ br,
                              const float* __restrict__ Wn, const float* __restrict__ bn) {
    __shared__ float sWr[2048], sWn[2048];
    __shared__ float sbr[8], sbn[8], sAvg[8];
    __shared__ int scnt[8], sbase[8];
    int tid = threadIdx.x;
    int i = blockIdx.x * 256 + tid;
    int b = i >> 12;
    for (int j = tid; j < 2048; j += 256) { sWr[j] = Wr[j]; sWn[j] = Wn[j]; }
    if (tid < 8) {
        sbr[tid] = br[tid]; sbn[tid] = bn[tid];
        sAvg[tid] = g_avglogit[b * 8 + tid];
        scnt[tid] = 0;
    }
    __syncthreads();

    float ar[8] = {0, 0, 0, 0, 0, 0, 0, 0};
    float an[8] = {0, 0, 0, 0, 0, 0, 0, 0};
    const float4* xp = (const float4*)(x + (size_t)i * DIM);

#define ROUT_STEP(xc, kk)                                                            \
    {                                                                                \
        float4 w0 = *(const float4*)&sWr[(kk) * 8];                                  \
        float4 w1 = *(const float4*)&sWr[(kk) * 8 + 4];                              \
        float4 u0 = *(const float4*)&sWn[(kk) * 8];                                  \
        float4 u1 = *(const float4*)&sWn[(kk) * 8 + 4];                              \
        ar[0] += (xc) * w0.x; ar[1] += (xc) * w0.y; ar[2] += (xc) * w0.z;            \
        ar[3] += (xc) * w0.w; ar[4] += (xc) * w1.x; ar[5] += (xc) * w1.y;            \
        ar[6] += (xc) * w1.z; ar[7] += (xc) * w1.w;                                  \
        an[0] += (xc) * u0.x; an[1] += (xc) * u0.y; an[2] += (xc) * u0.z;            \
        an[3] += (xc) * u0.w; an[4] += (xc) * u1.x; an[5] += (xc) * u1.y;            \
        an[6] += (xc) * u1.z; an[7] += (xc) * u1.w;                                  \
    }

#pragma unroll 4
    for (int k4 = 0; k4 < 64; k4++) {
        float4 xv = xp[k4];
        int k = k4 * 4;
        ROUT_STEP(xv.x, k + 0);
        ROUT_STEP(xv.y, k + 1);
        ROUT_STEP(xv.z, k + 2);
        ROUT_STEP(xv.w, k + 3);
    }
#undef ROUT_STEP

    float noisy[8];
    const float* np = noise + (size_t)i * 8;
#pragma unroll
    for (int e = 0; e < 8; e++) {
        float lg = ar[e] + sbr[e] + sAvg[e];
        float z = an[e] + sbn[e];
        float sp = fmaxf(z, 0.f) + log1pf(expf(-fabsf(z)));
        noisy[e] = lg + np[e] * sp;
    }
    int i1 = 0; float v1 = noisy[0];
#pragma unroll
    for (int e = 1; e < 8; e++) if (noisy[e] > v1) { v1 = noisy[e]; i1 = e; }
    int i2 = -1; float v2 = -INFINITY;
#pragma unroll
    for (int e = 0; e < 8; e++) if (e != i1 && noisy[e] > v2) { v2 = noisy[e]; i2 = e; }

    float t = expf(v2 - v1);
    int es; float g;
    if (i1 > i2) { es = i1; g = 1.f / (1.f + t); }
    else         { es = i2; g = t / (1.f + t); }

    int pl = atomicAdd(&scnt[es], 1);
    __syncthreads();
    if (tid < 8) sbase[tid] = atomicAdd(&g_cnt[tid], scnt[tid]);
    __syncthreads();
    g_tok[es * NTOK + sbase[es] + pl] = i;
    g_gate[i] = g;
}

// ---------------- K4: per-expert tile offsets ----------------
__global__ void scan_kernel() {
    if (threadIdx.x == 0) {
        int tb = 0;
        for (int e = 0; e < NE; e++) {
            g_tileBase[e] = tb;
            tb += (g_cnt[e] + 127) >> 7;
        }
        g_tileBase[NE] = tb;
    }
}

// ---------------- tile metadata helper ----------------
__device__ __forceinline__ void tile_meta(int bx, int* sMeta) {
    int e = -1, rem = 0, tokbase = 0;
    if (bx < g_tileBase[NE]) {
        e = 0;
        while (bx >= g_tileBase[e + 1]) e++;
        int lt = bx - g_tileBase[e];
        tokbase = e * NTOK + lt * 128;
        rem = g_cnt[e] - lt * 128;
    }
    sMeta[0] = e; sMeta[1] = tokbase; sMeta[2] = rem;
}

// ==================== GEMM core: cp.async + ldmatrix, BK=64, 3 stages (R8 config) ====
// Stage: A [128 rows][128 B] SW-swizzled at +0; B [128 rows][128 B] at +16384.
#define STAGE_BYTES 32768
#define SMEM_GEMM (3 * STAGE_BYTES)  // 96 KB

#define GEMM_LOAD(st, cc)                                                     \
    do {                                                                      \
        uint32_t _ab = smemBase + (st) * STAGE_BYTES;                         \
        int _kt = (cc) * 64;                                                  \
        _Pragma("unroll")                                                     \
        for (int i = 0; i < 4; i++) cpa16(_ab + aDst[i], aSrc[i] + _kt);      \
        _Pragma("unroll")                                                     \
        for (int i = 0; i < 4; i++) cpa16(_ab + bDst[i], bSrc[i] + _kt);      \
    } while (0)

#define GEMM_COMPUTE(st)                                                      \
    do {                                                                      \
        uint32_t _ab = smemBase + (st) * STAGE_BYTES;                         \
        _Pragma("unroll")                                                     \
        for (int ks = 0; ks < 4; ks++) {                                      \
            uint32_t af[4][4], bf[4][2];                                      \
            _Pragma("unroll")                                                 \
            for (int mt = 0; mt < 4; mt++)                                    \
                ldsm4(af[mt], _ab + aLdBase + mt * 2048 +                     \
                              ((uint32_t)((2 * ks + hiA) ^ r7A) << 4));       \
            _Pragma("unroll")                                                 \
            for (int nt = 0; nt < 4; nt++)                                    \
                ldsm2(bf[nt], _ab + 16384 + bLdBase + nt * 1024 +             \
                              ((uint32_t)((2 * ks + hiB) ^ r7B) << 4));       \
            _Pragma("unroll")                                                 \
            for (int mt = 0; mt < 4; mt++)                                    \
                _Pragma("unroll")                                             \
                for (int nt = 0; nt < 4; nt++)                                \
                    mma_f16(acc[mt][nt], af[mt], bf[nt]);                     \
        }                                                                     \
    } while (0)

// ================ gemmA: hidden = relu(X @ W1 + b1) ================
__global__ void __launch_bounds__(256, 2)
gemmA_kernel(const float* __restrict__ b1) {
    extern __shared__ __align__(16) char dsm[];
    __shared__ int rowTok[128];
    __shared__ int sMeta[3];

    const int tid = threadIdx.x;
    if (tid == 0) tile_meta(blockIdx.x, sMeta);
    __syncthreads();
    const int e = sMeta[0];
    if (e < 0) return;
    const int rem = sMeta[2];
    const int n0 = blockIdx.y * 128;
    if (tid < 128) rowTok[tid] = (tid < rem) ? g_tok[sMeta[1] + tid] : g_tok[sMeta[1]];
    __syncthreads();

    const int lane = tid & 31, wid = tid >> 5;
    const int wm = wid >> 2, wn = wid & 3;
    const int mbase = wm * 64, nbase = wn * 32;
    const int lr = lane >> 2, lc = lane & 3;

    const uint32_t smemBase = smem_u32(dsm);

    const __half* aSrc[4];
    const __half* bSrc[4];
    uint32_t aDst[4], bDst[4];
#pragma unroll
    for (int i = 0; i < 4; i++) {
        int idx = tid + 256 * i;
        int m = idx >> 3, ch = idx & 7;
        aSrc[i] = g_xh + (size_t)rowTok[m] * DIM + ch * 8;
        aDst[i] = (uint32_t)(m * 128 + ((ch ^ (m & 7)) << 4));
        bSrc[i] = g_W1h + (size_t)e * HID * DIM + (size_t)(n0 + m) * DIM + ch * 8;
        bDst[i] = (uint32_t)(16384 + m * 128 + ((ch ^ (m & 7)) << 4));
    }
    const int r7A = lane & 7, hiA = lane >> 4;
    const uint32_t aLdBase = (uint32_t)((mbase + (lane & 15)) * 128);
    const int r7B = lane & 7, hiB = (lane >> 3) & 1;
    const uint32_t bLdBase = (uint32_t)((nbase + (lane & 7)) * 128);

    float acc[4][4][4];
#pragma unroll
    for (int a = 0; a < 4; a++)
#pragma unroll
        for (int b = 0; b < 4; b++)
#pragma unroll
            for (int c = 0; c < 4; c++) acc[a][b][c] = 0.f;

    GEMM_LOAD(0, 0); CP_COMMIT();
    GEMM_LOAD(1, 1); CP_COMMIT();
#pragma unroll
    for (int c = 0; c < 4; c++) {
        CP_WAIT1();
        __syncthreads();
        if (c + 2 < 4) GEMM_LOAD((c + 2) % 3, c + 2);
        CP_COMMIT();
        GEMM_COMPUTE(c % 3);
    }

    // epilogue: acc -> Hs (half2, row stride 68 u32) -> coalesced STG
    __syncthreads();
    uint32_t* Hs = (uint32_t*)dsm;
    const float* bg = b1 + (size_t)e * HID + n0;
#pragma unroll
    for (int nt = 0; nt < 4; nt++) {
        int col = nbase + nt * 8 + lc * 2;
        float bb0 = __ldg(bg + col), bb1 = __ldg(bg + col + 1);
        int chn = col >> 1;
#pragma unroll
        for (int mt = 0; mt < 4; mt++) {
            int r0 = mbase + mt * 16 + lr;
            Hs[r0 * 68 + chn] = pk2h(fmaxf(acc[mt][nt][0] + bb0, 0.f),
                                     fmaxf(acc[mt][nt][1] + bb1, 0.f));
            Hs[(r0 + 8) * 68 + chn] = pk2h(fmaxf(acc[mt][nt][2] + bb0, 0.f),
                                           fmaxf(acc[mt][nt][3] + bb1, 0.f));
        }
    }
    __syncthreads();
    __half* hp = g_hidden + ((size_t)blockIdx.x * 128) * HID + n0;
#pragma unroll
    for (int j = 0; j < 8; j++) {
        int U = tid + 256 * j;
        int row = U >> 4, c4 = U & 15;
        uint4 v = *(const uint4*)&Hs[row * 68 + c4 * 4];
        *(uint4*)(hp + (size_t)row * HID + c4 * 8) = v;
    }
}

// ================ gemmB: out = (hidden @ W2 + b2) * gate ================
__global__ void __launch_bounds__(256, 2)
gemmB_kernel(const float* __restrict__ b2, float* __restrict__ out) {
    extern __shared__ __align__(16) char dsm[];
    __shared__ int rowTok[128];
    __shared__ float sGate[128];
    __shared__ int sMeta[3];

    const int tid = threadIdx.x;
    if (tid == 0) tile_meta(blockIdx.x, sMeta);
    __syncthreads();
    const int e = sMeta[0];
    if (e < 0) return;
    const int rem = sMeta[2];
    const int ybase = blockIdx.y * 128;
    if (tid < 128) {
        int tr = (tid < rem) ? g_tok[sMeta[1] + tid] : -1;
        rowTok[tid] = tr;
        sGate[tid] = (tr >= 0) ? g_gate[tr] : 0.f;
    }
    __syncthreads();

    const int lane = tid & 31, wid = tid >> 5;
    const int wm = wid >> 2, wn = wid & 3;
    const int mbase = wm * 64, nbase = wn * 32;
    const int lr = lane >> 2, lc = lane & 3;

    const uint32_t smemBase = smem_u32(dsm);

    const __half* aSrc[4];
    const __half* bSrc[4];
    uint32_t aDst[4], bDst[4];
#pragma unroll
    for (int i = 0; i < 4; i++) {
        int idx = tid + 256 * i;
        int m = idx >> 3, ch = idx & 7;
        aSrc[i] = g_hidden + ((size_t)blockIdx.x * 128 + m) * HID + ch * 8;
        aDst[i] = (uint32_t)(m * 128 + ((ch ^ (m & 7)) << 4));
        bSrc[i] = g_W2h + (size_t)e * DIM * HID + (size_t)(ybase + m) * HID + ch * 8;
        bDst[i] = (uint32_t)(16384 + m * 128 + ((ch ^ (m & 7)) << 4));
    }
    const int r7A = lane & 7, hiA = lane >> 4;
    const uint32_t aLdBase = (uint32_t)((mbase + (lane & 15)) * 128);
    const int r7B = lane & 7, hiB = (lane >> 3) & 1;
    const uint32_t bLdBase = (uint32_t)((nbase + (lane & 7)) * 128);

    float acc[4][4][4];
#pragma unroll
    for (int a = 0; a < 4; a++)
#pragma unroll
        for (int b = 0; b < 4; b++)
#pragma unroll
            for (int c = 0; c < 4; c++) acc[a][b][c] = 0.f;

    GEMM_LOAD(0, 0); CP_COMMIT();
    GEMM_LOAD(1, 1); CP_COMMIT();
    for (int c = 0; c < 16; c++) {
        CP_WAIT1();
        __syncthreads();
        if (c + 2 < 16) GEMM_LOAD((c + 2) % 3, c + 2);
        CP_COMMIT();
        GEMM_COMPUTE(c % 3);
    }

    // epilogue: bias + gate -> scattered out rows
    const float* bg = b2 + (size_t)e * DIM + ybase;
#pragma unroll
    for (int nt = 0; nt < 4; nt++) {
        int col = nbase + nt * 8 + lc * 2;
        float bb0 = __ldg(bg + col), bb1 = __ldg(bg + col + 1);
#pragma unroll
        for (int mt = 0; mt < 4; mt++) {
            int r0 = mbase + mt * 16 + lr;
            if (r0 < rem) {
                float g = sGate[r0];
                float2 o;
                o.x = (acc[mt][nt][0] + bb0) * g;
                o.y = (acc[mt][nt][1] + bb1) * g;
                *(float2*)&out[(size_t)rowTok[r0] * DIM + ybase + col] = o;
            }
            int r1 = r0 + 8;
            if (r1 < rem) {
                float g = sGate[r1];
                float2 o;
                o.x = (acc[mt][nt][2] + bb0) * g;
                o.y = (acc[mt][nt][3] + bb1) * g;
                *(float2*)&out[(size_t)rowTok[r1] * DIM + ybase + col] = o;
            }
        }
    }
}

// ---------------- launch ----------------
extern "C" void kernel_launch(void* const* d_in, const int* in_sizes, int n_in,
                              void* d_out, int out_size) {
    const float* x     = (const float*)d_in[0];
    const float* noise = (const float*)d_in[1];
    const float* Wr    = (const float*)d_in[2];
    const float* br    = (const float*)d_in[3];
    const float* Wa    = (const float*)d_in[4];
    const float* ba    = (const float*)d_in[5];
    const float* Wn    = (const float*)d_in[6];
    const float* bn    = (const float*)d_in[7];
    const float* W1    = (const float*)d_in[8];
    const float* b1    = (const float*)d_in[9];
    const float* W2    = (const float*)d_in[10];
    const float* b2    = (const float*)d_in[11];
    float* out = (float*)d_out;

    cudaFuncSetAttribute(gemmA_kernel, cudaFuncAttributeMaxDynamicSharedMemorySize, SMEM_GEMM);
    cudaFuncSetAttribute(gemmB_kernel, cudaFuncAttributeMaxDynamicSharedMemorySize, SMEM_GEMM);

    convXpool_kernel<<<dim3(256, 16), 256>>>(x);
    convW1_kernel<<<dim3(HID / 32, DIM / 32, NE), dim3(32, 8)>>>(W1);
    convW2_kernel<<<dim3(DIM / 32, HID / 32, NE), dim3(32, 8)>>>(W2);
    prep_kernel<<<128, 256>>>(Wa, ba);
    router_kernel<<<256, 256>>>(x, noise, Wr, br, Wn, bn);
    scan_kernel<<<1, 1>>>();
    gemmA_kernel<<<dim3(MAXTILES, 8), 256, SMEM_GEMM>>>(b1);
    gemmB_kernel<<<dim3(MAXTILES, 2), 256, SMEM_GEMM>>>(b2, out);
}